// round 2
// baseline (speedup 1.0000x reference)
#include <cuda_runtime.h>

// Problem constants
#define B_  256
#define A_  128
#define D_  5
#define FA_ 256
#define FB_ 64
#define C_  256
#define F_  (FA_ + FB_)     // 320
#define NROWS (B_ * A_)     // 32768
#define TILE 8
#define MAXT ((NROWS + TILE - 1) / TILE)   // 4096
#define NSLOTS (D_ * MAXT)                 // 20480

// Scratch (static device memory — allocation-free)
__device__ int   g_cnt[D_];
__device__ int   g_rows[D_ * NROWS];
__device__ float g_feat[(size_t)NROWS * F_];

// ---------------------------------------------------------------------------
__global__ void zero_counters() {
    if (threadIdx.x < D_) g_cnt[threadIdx.x] = 0;
}

// ---------------------------------------------------------------------------
// Per-row: classify by degree. deg>=5 rows -> zero output and done.
// Active rows -> build feat[320] into g_feat, append row id to per-deg list.
__global__ __launch_bounds__(256) void prep_kernel(
    const float* __restrict__ atoms,   // [B, A, FA]
    const float* __restrict__ bonds,   // [B, A, D, FB]
    const int*   __restrict__ edges,   // [B, A, D]
    float*       __restrict__ out)     // [B, A, C]
{
    const int row = blockIdx.x;
    const int tid = threadIdx.x;

    __shared__ int s_e[D_];
    if (tid < D_) s_e[tid] = edges[row * D_ + tid];
    __syncthreads();

    const int e0 = s_e[0], e1 = s_e[1], e2 = s_e[2], e3 = s_e[3], e4 = s_e[4];
    const int deg = (e0 >= 0) + (e1 >= 0) + (e2 >= 0) + (e3 >= 0) + (e4 >= 0);

    if (deg >= D_) {
        // mask (deg == 0..4) never matches -> exact zero row
        if (tid < C_ / 4) {
            reinterpret_cast<float4*>(out + (size_t)row * C_)[tid] =
                make_float4(0.f, 0.f, 0.f, 0.f);
        }
        return;
    }

    const int batch = row / A_;
    const float* abase = atoms + (size_t)batch * A_ * FA_;

    // summed_atom (f = tid, FA_ == 256 == blockDim.x)
    {
        float s = atoms[(size_t)row * FA_ + tid];
        if (e0 >= 0) s += abase[(size_t)e0 * FA_ + tid];
        if (e1 >= 0) s += abase[(size_t)e1 * FA_ + tid];
        if (e2 >= 0) s += abase[(size_t)e2 * FA_ + tid];
        if (e3 >= 0) s += abase[(size_t)e3 * FA_ + tid];
        if (e4 >= 0) s += abase[(size_t)e4 * FA_ + tid];
        g_feat[(size_t)row * F_ + tid] = s;
    }
    // summed_bond (unconditional sum over D slots, per reference)
    if (tid < FB_) {
        const float* bb = bonds + (size_t)row * D_ * FB_ + tid;
        g_feat[(size_t)row * F_ + FA_ + tid] =
            bb[0] + bb[FB_] + bb[2 * FB_] + bb[3 * FB_] + bb[4 * FB_];
    }
    if (tid == 0) {
        int p = atomicAdd(&g_cnt[deg], 1);
        g_rows[deg * NROWS + p] = row;
    }
}

// ---------------------------------------------------------------------------
// Tiled GEMM over compacted active rows.
// Work item (slot) = (tile, deg), tile-major so active slots are dense/spread.
// Each CTA: 8 rows x 256 cols, thread c holds 8 accumulators, W read once per f.
__global__ __launch_bounds__(256) void gemm_kernel(
    const float* __restrict__ W,       // [D, F, C]
    const float* __restrict__ bias,    // [D, C]
    float*       __restrict__ out)     // [B, A, C]
{
    const int tid = threadIdx.x;

    // Read all counts once; loop validity checks are then pure arithmetic.
    int cnts[D_];
    #pragma unroll
    for (int d = 0; d < D_; ++d) cnts[d] = g_cnt[d];

    __shared__ float s_feat[TILE][F_];
    __shared__ int   s_rows[TILE];

    for (int slot = blockIdx.x; slot < NSLOTS; slot += gridDim.x) {
        const int deg  = slot % D_;
        const int tile = slot / D_;
        const int cnt  = cnts[deg];
        const int base = tile * TILE;
        if (base >= cnt) continue;
        const int nrows = min(TILE, cnt - base);

        if (tid < TILE)
            s_rows[tid] = (tid < nrows) ? g_rows[deg * NROWS + base + tid] : -1;
        __syncthreads();

        // Stage feats for the tile (coalesced per row)
        #pragma unroll
        for (int r = 0; r < TILE; ++r) {
            const int row = s_rows[r];
            if (row >= 0) {
                for (int f = tid; f < F_; f += 256)
                    s_feat[r][f] = g_feat[(size_t)row * F_ + f];
            } else {
                for (int f = tid; f < F_; f += 256)
                    s_feat[r][f] = 0.f;
            }
        }
        __syncthreads();

        // GEMM: acc[r] = bias + sum_f feat[r][f] * W[deg][f][c]
        const float* Wd = W + (size_t)deg * F_ * C_ + tid;
        const float  bv = bias[deg * C_ + tid];
        float acc[TILE];
        #pragma unroll
        for (int r = 0; r < TILE; ++r) acc[r] = bv;

        for (int f = 0; f < F_; f += 4) {
            const float w0 = Wd[(size_t)(f + 0) * C_];
            const float w1 = Wd[(size_t)(f + 1) * C_];
            const float w2 = Wd[(size_t)(f + 2) * C_];
            const float w3 = Wd[(size_t)(f + 3) * C_];
            #pragma unroll
            for (int r = 0; r < TILE; ++r) {
                const float4 fv = *reinterpret_cast<const float4*>(&s_feat[r][f]);
                acc[r] = fmaf(fv.x, w0, acc[r]);
                acc[r] = fmaf(fv.y, w1, acc[r]);
                acc[r] = fmaf(fv.z, w2, acc[r]);
                acc[r] = fmaf(fv.w, w3, acc[r]);
            }
        }

        #pragma unroll
        for (int r = 0; r < TILE; ++r) {
            const int row = s_rows[r];
            if (row >= 0)
                out[(size_t)row * C_ + tid] = fmaxf(acc[r], 0.f);
        }
        __syncthreads();   // smem reuse across slots
    }
}

// ---------------------------------------------------------------------------
extern "C" void kernel_launch(void* const* d_in, const int* in_sizes, int n_in,
                              void* d_out, int out_size)
{
    const float* atoms = (const float*)d_in[0];
    const float* bonds = (const float*)d_in[1];
    const int*   edges = (const int*)  d_in[2];
    const float* W     = (const float*)d_in[3];
    const float* bias  = (const float*)d_in[4];
    float* out = (float*)d_out;

    zero_counters<<<1, 32>>>();
    prep_kernel<<<NROWS, 256>>>(atoms, bonds, edges, out);
    gemm_kernel<<<148 * 8, 256>>>(W, bias, out);
}